// round 6
// baseline (speedup 1.0000x reference)
#include <cuda_runtime.h>

#define DIM  480
#define WPB  8          // warps per block
#define SEGV 88         // segment-region float4 per row

__global__ __launch_bounds__(WPB * 32) void eqln_kernel(
    const float* __restrict__ x,
    const float* __restrict__ w,
    const float* __restrict__ bias,
    float* __restrict__ out,
    int n)
{
    __shared__ float4 sres4[WPB][SEGV];    // staged RESULTS only (coalesced store)

    const int warp = threadIdx.x >> 5;
    const int lane = threadIdx.x & 31;
    float* sres = reinterpret_cast<float*>(sres4[warp]);

    const int warp_id   = blockIdx.x * WPB + warp;
    const int warp_step = gridDim.x * WPB;

    for (int row = warp_id; row < n; row += warp_step) {
        const size_t off = (size_t)row * DIM;
        const float* src = x + off;
        float* dst       = out + off;

        // ---- front-batch ALL loads (9 per lane; lane-private segment data) ----
        float4 q = __ldcs(reinterpret_cast<const float4*>(src) + lane);

        const float2* p3 = reinterpret_cast<const float2*>(src + 128 + 6 * lane);
        float2 t0 = __ldcs(p3 + 0);
        float2 t1 = __ldcs(p3 + 1);
        float2 t2 = __ldcs(p3 + 2);

        const float* p5 = src + 320 + 5 * lane;
        float u0 = __ldcs(p5 + 0);
        float u1 = __ldcs(p5 + 1);
        float u2 = __ldcs(p5 + 2);
        float u3 = __ldcs(p5 + 3);
        float u4 = __ldcs(p5 + 4);

        // ---- segment norms in registers ----
        {   // seg 2l: t0.x t0.y t1.x
            float m  = (t0.x + t0.y + t1.x) * (1.0f / 3.0f);
            float da = t0.x - m, db = t0.y - m, dc = t1.x - m;
            float rv = rsqrtf((da * da + db * db + dc * dc) * (1.0f / 3.0f) + 1e-5f);
            t0.x = da * rv; t0.y = db * rv; t1.x = dc * rv;
        }
        {   // seg 2l+1: t1.y t2.x t2.y
            float m  = (t1.y + t2.x + t2.y) * (1.0f / 3.0f);
            float da = t1.y - m, db = t2.x - m, dc = t2.y - m;
            float rv = rsqrtf((da * da + db * db + dc * dc) * (1.0f / 3.0f) + 1e-5f);
            t1.y = da * rv; t2.x = db * rv; t2.y = dc * rv;
        }
        {   // seg l of 5
            float m  = (u0 + u1 + u2 + u3 + u4) * 0.2f;
            float da = u0 - m, db = u1 - m, dc = u2 - m, dd = u3 - m, de = u4 - m;
            float rv = rsqrtf((da * da + db * db + dc * dc + dd * dd + de * de) * 0.2f + 1e-5f);
            u0 = da * rv; u1 = db * rv; u2 = dc * rv; u3 = dd * rv; u4 = de * rv;
        }

        // ---- stage results into smem ----
        {
            float2* r3 = reinterpret_cast<float2*>(sres + 6 * lane);
            r3[0] = t0; r3[1] = t1; r3[2] = t2;
            float* r5 = sres + 192 + 5 * lane;
            r5[0] = u0; r5[1] = u1; r5[2] = u2; r5[3] = u3; r5[4] = u4;
        }

        // ---- LayerNorm over first 128 (shfl latency overlaps STS drain) ----
        float s  = q.x + q.y + q.z + q.w;
        float ss = q.x * q.x + q.y * q.y + q.z * q.z + q.w * q.w;
#pragma unroll
        for (int o = 16; o > 0; o >>= 1) {
            s  += __shfl_xor_sync(0xffffffffu, s,  o);
            ss += __shfl_xor_sync(0xffffffffu, ss, o);
        }
        const float mean = s * (1.0f / 128.0f);
        const float var  = ss * (1.0f / 128.0f) - mean * mean;
        const float rstd = rsqrtf(var + 1e-5f);
        {
            const int c = lane * 4;
            float4 r;
            r.x = (q.x - mean) * rstd * __ldg(w + c + 0) + __ldg(bias + c + 0);
            r.y = (q.y - mean) * rstd * __ldg(w + c + 1) + __ldg(bias + c + 1);
            r.z = (q.z - mean) * rstd * __ldg(w + c + 2) + __ldg(bias + c + 2);
            r.w = (q.w - mean) * rstd * __ldg(w + c + 3) + __ldg(bias + c + 3);
            __stcs(reinterpret_cast<float4*>(dst) + lane, r);
        }

        __syncwarp();

        // ---- cooperative, fully-coalesced float4 store of segment results ----
        float4* dst4 = reinterpret_cast<float4*>(dst);
        __stcs(dst4 + 32 + lane, sres4[warp][lane]);
        __stcs(dst4 + 64 + lane, sres4[warp][lane + 32]);
        if (lane < SEGV - 64)
            __stcs(dst4 + 96 + lane, sres4[warp][lane + 64]);

        __syncwarp();   // results consumed before next iteration overwrites sres
    }
}

extern "C" void kernel_launch(void* const* d_in, const int* in_sizes, int n_in,
                              void* d_out, int out_size)
{
    const float* x    = (const float*)d_in[0];
    const float* w    = (const float*)d_in[1];
    const float* bias = (const float*)d_in[2];
    float* out        = (float*)d_out;

    int n = in_sizes[0] / DIM;
    // persistent grid: 152 SMs x 8 resident CTAs (256 thr, 32 regs) = one wave
    int blocks = 152 * 8;
    eqln_kernel<<<blocks, WPB * 32>>>(x, w, bias, out, n);
}

// round 8
// speedup vs baseline: 1.1244x; 1.1244x over previous
#include <cuda_runtime.h>

#define DIM  480
#define WPB  8          // warps per block; each warp does 2 rows
#define SEGV 88         // segment-region float4 per row

__global__ __launch_bounds__(WPB * 32) void eqln_kernel(
    const float* __restrict__ x,
    const float* __restrict__ w,
    const float* __restrict__ bias,
    float* __restrict__ out,
    int n)
{
    __shared__ float4 sres4[WPB][2][SEGV];   // staged results, 2 rows per warp

    const int warp = threadIdx.x >> 5;
    const int lane = threadIdx.x & 31;
    const int row0 = (blockIdx.x * WPB + warp) * 2;
    if (row0 >= n) return;

    const float* srcA = x + (size_t)row0 * DIM;
    const float* srcB = srcA + DIM;

    // ================= front-batch ALL 18 loads (both rows) =================
    float4 qA = __ldcs(reinterpret_cast<const float4*>(srcA) + lane);
    const float2* p3A = reinterpret_cast<const float2*>(srcA + 128 + 6 * lane);
    float2 a0 = __ldcs(p3A + 0);
    float2 a1 = __ldcs(p3A + 1);
    float2 a2 = __ldcs(p3A + 2);
    const float* p5A = srcA + 320 + 5 * lane;
    float x0 = __ldcs(p5A + 0);
    float x1 = __ldcs(p5A + 1);
    float x2 = __ldcs(p5A + 2);
    float x3 = __ldcs(p5A + 3);
    float x4 = __ldcs(p5A + 4);

    float4 qB = __ldcs(reinterpret_cast<const float4*>(srcB) + lane);
    const float2* p3B = reinterpret_cast<const float2*>(srcB + 128 + 6 * lane);
    float2 b0 = __ldcs(p3B + 0);
    float2 b1 = __ldcs(p3B + 1);
    float2 b2 = __ldcs(p3B + 2);
    const float* p5B = srcB + 320 + 5 * lane;
    float y0 = __ldcs(p5B + 0);
    float y1 = __ldcs(p5B + 1);
    float y2 = __ldcs(p5B + 2);
    float y3 = __ldcs(p5B + 3);
    float y4 = __ldcs(p5B + 4);

    // ================= segment norms + staging, row A =================
    {
        float m  = (a0.x + a0.y + a1.x) * (1.0f / 3.0f);
        float da = a0.x - m, db = a0.y - m, dc = a1.x - m;
        float rv = rsqrtf((da * da + db * db + dc * dc) * (1.0f / 3.0f) + 1e-5f);
        a0.x = da * rv; a0.y = db * rv; a1.x = dc * rv;
    }
    {
        float m  = (a1.y + a2.x + a2.y) * (1.0f / 3.0f);
        float da = a1.y - m, db = a2.x - m, dc = a2.y - m;
        float rv = rsqrtf((da * da + db * db + dc * dc) * (1.0f / 3.0f) + 1e-5f);
        a1.y = da * rv; a2.x = db * rv; a2.y = dc * rv;
    }
    {
        float m  = (x0 + x1 + x2 + x3 + x4) * 0.2f;
        float da = x0 - m, db = x1 - m, dc = x2 - m, dd = x3 - m, de = x4 - m;
        float rv = rsqrtf((da * da + db * db + dc * dc + dd * dd + de * de) * 0.2f + 1e-5f);
        x0 = da * rv; x1 = db * rv; x2 = dc * rv; x3 = dd * rv; x4 = de * rv;
    }
    {
        float* sres = reinterpret_cast<float*>(sres4[warp][0]);
        float2* r3 = reinterpret_cast<float2*>(sres + 6 * lane);
        r3[0] = a0; r3[1] = a1; r3[2] = a2;
        float* r5 = sres + 192 + 5 * lane;
        r5[0] = x0; r5[1] = x1; r5[2] = x2; r5[3] = x3; r5[4] = x4;
    }

    // ================= segment norms + staging, row B =================
    {
        float m  = (b0.x + b0.y + b1.x) * (1.0f / 3.0f);
        float da = b0.x - m, db = b0.y - m, dc = b1.x - m;
        float rv = rsqrtf((da * da + db * db + dc * dc) * (1.0f / 3.0f) + 1e-5f);
        b0.x = da * rv; b0.y = db * rv; b1.x = dc * rv;
    }
    {
        float m  = (b1.y + b2.x + b2.y) * (1.0f / 3.0f);
        float da = b1.y - m, db = b2.x - m, dc = b2.y - m;
        float rv = rsqrtf((da * da + db * db + dc * dc) * (1.0f / 3.0f) + 1e-5f);
        b1.y = da * rv; b2.x = db * rv; b2.y = dc * rv;
    }
    {
        float m  = (y0 + y1 + y2 + y3 + y4) * 0.2f;
        float da = y0 - m, db = y1 - m, dc = y2 - m, dd = y3 - m, de = y4 - m;
        float rv = rsqrtf((da * da + db * db + dc * dc + dd * dd + de * de) * 0.2f + 1e-5f);
        y0 = da * rv; y1 = db * rv; y2 = dc * rv; y3 = dd * rv; y4 = de * rv;
    }
    {
        float* sres = reinterpret_cast<float*>(sres4[warp][1]);
        float2* r3 = reinterpret_cast<float2*>(sres + 6 * lane);
        r3[0] = b0; r3[1] = b1; r3[2] = b2;
        float* r5 = sres + 192 + 5 * lane;
        r5[0] = y0; r5[1] = y1; r5[2] = y2; r5[3] = y3; r5[4] = y4;
    }

    // ================= LayerNorm both rows (shfl overlaps STS drain) =================
    const int c = lane * 4;
    const float w0 = __ldg(w + c + 0), w1 = __ldg(w + c + 1);
    const float w2 = __ldg(w + c + 2), w3 = __ldg(w + c + 3);
    const float g0 = __ldg(bias + c + 0), g1 = __ldg(bias + c + 1);
    const float g2 = __ldg(bias + c + 2), g3 = __ldg(bias + c + 3);

    float sA  = qA.x + qA.y + qA.z + qA.w;
    float ssA = qA.x * qA.x + qA.y * qA.y + qA.z * qA.z + qA.w * qA.w;
    float sB  = qB.x + qB.y + qB.z + qB.w;
    float ssB = qB.x * qB.x + qB.y * qB.y + qB.z * qB.z + qB.w * qB.w;
#pragma unroll
    for (int o = 16; o > 0; o >>= 1) {
        sA  += __shfl_xor_sync(0xffffffffu, sA,  o);
        ssA += __shfl_xor_sync(0xffffffffu, ssA, o);
        sB  += __shfl_xor_sync(0xffffffffu, sB,  o);
        ssB += __shfl_xor_sync(0xffffffffu, ssB, o);
    }
    float* dstA = out + (size_t)row0 * DIM;
    float* dstB = dstA + DIM;
    {
        const float mean = sA * (1.0f / 128.0f);
        const float var  = ssA * (1.0f / 128.0f) - mean * mean;
        const float rstd = rsqrtf(var + 1e-5f);
        float4 r;
        r.x = (qA.x - mean) * rstd * w0 + g0;
        r.y = (qA.y - mean) * rstd * w1 + g1;
        r.z = (qA.z - mean) * rstd * w2 + g2;
        r.w = (qA.w - mean) * rstd * w3 + g3;
        __stcs(reinterpret_cast<float4*>(dstA) + lane, r);
    }
    {
        const float mean = sB * (1.0f / 128.0f);
        const float var  = ssB * (1.0f / 128.0f) - mean * mean;
        const float rstd = rsqrtf(var + 1e-5f);
        float4 r;
        r.x = (qB.x - mean) * rstd * w0 + g0;
        r.y = (qB.y - mean) * rstd * w1 + g1;
        r.z = (qB.z - mean) * rstd * w2 + g2;
        r.w = (qB.w - mean) * rstd * w3 + g3;
        __stcs(reinterpret_cast<float4*>(dstB) + lane, r);
    }

    __syncwarp();

    // ================= cooperative coalesced float4 stores, both rows =================
    float4* dA4 = reinterpret_cast<float4*>(dstA);
    __stcs(dA4 + 32 + lane, sres4[warp][0][lane]);
    __stcs(dA4 + 64 + lane, sres4[warp][0][lane + 32]);
    if (lane < SEGV - 64)
        __stcs(dA4 + 96 + lane, sres4[warp][0][lane + 64]);

    float4* dB4 = reinterpret_cast<float4*>(dstB);
    __stcs(dB4 + 32 + lane, sres4[warp][1][lane]);
    __stcs(dB4 + 64 + lane, sres4[warp][1][lane + 32]);
    if (lane < SEGV - 64)
        __stcs(dB4 + 96 + lane, sres4[warp][1][lane + 64]);
}

extern "C" void kernel_launch(void* const* d_in, const int* in_sizes, int n_in,
                              void* d_out, int out_size)
{
    const float* x    = (const float*)d_in[0];
    const float* w    = (const float*)d_in[1];
    const float* bias = (const float*)d_in[2];
    float* out        = (float*)d_out;

    int n = in_sizes[0] / DIM;
    int rows_per_block = WPB * 2;
    int blocks = (n + rows_per_block - 1) / rows_per_block;
    eqln_kernel<<<blocks, WPB * 32>>>(x, w, bias, out, n);
}